// round 10
// baseline (speedup 1.0000x reference)
#include <cuda_runtime.h>

#define T_STEPS 64
#define N_INJ 8
#define SID 7
#define BLOCK 224
#define GRID 147
#define NWARP 7

#define SM_T  0
#define SM_SE 1024
#define SM_CG (SM_SE + 14336)            // 224 rows * 16 f * 4B
#define SM_TOTAL (SM_CG + NWARP*8192)    // 72704 B

typedef unsigned u32;

__device__ __forceinline__ void bf16split2(float x0, float x1, u32& h, u32& l) {
    asm("cvt.rn.bf16x2.f32 %0, %1, %2;" : "=r"(h) : "f"(x1), "f"(x0));
    float h0 = __uint_as_float(h << 16);
    float h1 = __uint_as_float(h & 0xffff0000u);
    asm("cvt.rn.bf16x2.f32 %0, %1, %2;" : "=r"(l) : "f"(x1 - h1), "f"(x0 - h0));
}
__device__ __forceinline__ float tanhap(float x) {
    float r; asm("tanh.approx.f32 %0,%1;" : "=f"(r) : "f"(x)); return r;
}
__device__ __forceinline__ void mma4(float& c0, float& c1, float& c2, float& c3,
                                     const u32* a, u32 b0, u32 b1) {
    asm volatile("mma.sync.aligned.m16n8k16.row.col.f32.bf16.bf16.f32 "
        "{%0,%1,%2,%3},{%4,%5,%6,%7},{%8,%9},{%0,%1,%2,%3};"
        : "+f"(c0), "+f"(c1), "+f"(c2), "+f"(c3)
        : "r"(a[0]), "r"(a[1]), "r"(a[2]), "r"(a[3]), "r"(b0), "r"(b1));
}

// one MLP eval: ys[16] (C-frag state) -> ko[16]; 3 independent split chains
__device__ __forceinline__ void feval(
    float tv, const float* __restrict__ ys, float* __restrict__ ko,
    const u32* __restrict__ b1h, const u32* __restrict__ b1l,
    const u32* __restrict__ b2h, const u32* __restrict__ b2l,
    const float* __restrict__ w1dA, const float* __restrict__ w1dB,
    const float* __restrict__ b2q, const char* __restrict__ cgT,
    const float* __restrict__ itm, const float* __restrict__ idn, int g)
{
    float dose = 0.f;
    #pragma unroll
    for (int n = 0; n < N_INJ; n++) {
        float d = tv - itm[n];
        dose += idn[n] * __expf(-0.5f * d * d);
    }
    dose = fminf(fmaxf(dose, 0.f), 100.f);

    #pragma unroll
    for (int mt = 0; mt < 2; mt++) {
        float d0 = __shfl_sync(0xffffffffu, dose, 16 * mt + g);
        float d1 = __shfl_sync(0xffffffffu, dose, 16 * mt + g + 8);
        const float* y = ys + mt * 8;
        u32 a1h[4], a1l[4];
        bf16split2(y[0], y[1], a1h[0], a1l[0]);
        bf16split2(y[2], y[3], a1h[1], a1l[1]);
        bf16split2(y[4], y[5], a1h[2], a1l[2]);
        bf16split2(y[6], y[7], a1h[3], a1l[3]);

        u32 a2h[16], a2l[16];
        #pragma unroll
        for (int nt = 0; nt < 8; nt++) {
            float4 cg = *(const float4*)(cgT + (mt * 8 + nt) * 512);
            // three independent accumulator chains (HH / HL / LH)
            float zA0 = fmaf(d0, w1dA[nt], cg.x);
            float zA1 = fmaf(d0, w1dB[nt], cg.y);
            float zA2 = fmaf(d1, w1dA[nt], cg.z);
            float zA3 = fmaf(d1, w1dB[nt], cg.w);
            float zB0 = 0.f, zB1 = 0.f, zB2 = 0.f, zB3 = 0.f;
            float zC0 = 0.f, zC1 = 0.f, zC2 = 0.f, zC3 = 0.f;
            mma4(zA0, zA1, zA2, zA3, a1h, b1h[nt * 2], b1h[nt * 2 + 1]);
            mma4(zB0, zB1, zB2, zB3, a1h, b1l[nt * 2], b1l[nt * 2 + 1]);
            mma4(zC0, zC1, zC2, zC3, a1l, b1h[nt * 2], b1h[nt * 2 + 1]);
            float t0 = tanhap(zA0 + zB0 + zC0);
            float t1 = tanhap(zA1 + zB1 + zC1);
            float t2 = tanhap(zA2 + zB2 + zC2);
            float t3 = tanhap(zA3 + zB3 + zC3);
            int base = (nt >> 1) * 4 + (nt & 1) * 2;
            bf16split2(t0, t1, a2h[base], a2l[base]);
            bf16split2(t2, t3, a2h[base + 1], a2l[base + 1]);
        }
        #pragma unroll
        for (int nt2 = 0; nt2 < 2; nt2++) {
            float cA0 = b2q[nt2 * 2], cA1 = b2q[nt2 * 2 + 1];
            float cA2 = cA0, cA3 = cA1;
            float cB0 = 0.f, cB1 = 0.f, cB2 = 0.f, cB3 = 0.f;
            float cC0 = 0.f, cC1 = 0.f, cC2 = 0.f, cC3 = 0.f;
            #pragma unroll
            for (int kt = 0; kt < 4; kt++) {
                const u32* bh = b2h + kt * 4 + nt2 * 2;
                const u32* bl = b2l + kt * 4 + nt2 * 2;
                mma4(cA0, cA1, cA2, cA3, a2h + kt * 4, bh[0], bh[1]);
                mma4(cB0, cB1, cB2, cB3, a2h + kt * 4, bl[0], bl[1]);
                mma4(cC0, cC1, cC2, cC3, a2l + kt * 4, bh[0], bh[1]);
            }
            ko[mt * 8 + nt2 * 4 + 0] = cA0 + cB0 + cC0;
            ko[mt * 8 + nt2 * 4 + 1] = cA1 + cB1 + cC1;
            ko[mt * 8 + nt2 * 4 + 2] = cA2 + cB2 + cC2;
            ko[mt * 8 + nt2 * 4 + 3] = cA3 + cB3 + cC3;
        }
    }
}

__device__ __forceinline__ void writeout(
    const float* __restrict__ h, const float* __restrict__ wrq, float brv,
    int rbase, int g, int c, int step, float* __restrict__ out)
{
    #pragma unroll
    for (int mt = 0; mt < 2; mt++)
    #pragma unroll
    for (int rh = 0; rh < 2; rh++) {
        float p = h[mt * 8 + rh * 2 + 0] * wrq[0] + h[mt * 8 + rh * 2 + 1] * wrq[1]
                + h[mt * 8 + 4 + rh * 2 + 0] * wrq[2] + h[mt * 8 + 4 + rh * 2 + 1] * wrq[3];
        p += __shfl_xor_sync(0xffffffffu, p, 1);
        p += __shfl_xor_sync(0xffffffffu, p, 2);
        if (c == 0)
            out[(rbase + 16 * mt + g + 8 * rh) * T_STEPS + step] = fmaxf(brv + p, 0.f);
    }
}

extern "C" __global__ void __launch_bounds__(BLOCK, 1)
neural_ode_66236985639756(
    const float* __restrict__ t_g,  const float* __restrict__ sf_g,
    const float* __restrict__ it_g, const float* __restrict__ id_g,
    const float* __restrict__ W_se, const float* __restrict__ b_se,
    const float* __restrict__ W_i,  const float* __restrict__ b_i,
    const float* __restrict__ W1,   const float* __restrict__ b1,
    const float* __restrict__ W2,   const float* __restrict__ b2,
    const float* __restrict__ Wr,   const float* __restrict__ br,
    float* __restrict__ out)
{
    extern __shared__ __align__(16) char smem[];
    float* smT = (float*)(smem + SM_T);
    float* seA = (float*)(smem + SM_SE);
    const int tid = threadIdx.x;
    const int wid = tid >> 5;
    const int lane = tid & 31;
    const int g = lane >> 2;
    const int c = lane & 3;
    const int gw = blockIdx.x * NWARP + wid;          // global warp id
    const bool valid = (gw < 1024);                   // 1024*32 = 32768 rows
    const int rbase = valid ? gw * 32 : 0;
    const int ro = rbase + lane;

    for (int i = tid; i < T_STEPS; i += BLOCK) smT[i] = t_g[i];

    // own-row static embed -> smem
    {
        float sfv[SID];
        #pragma unroll
        for (int i = 0; i < SID; i++) sfv[i] = sf_g[ro * SID + i];
        #pragma unroll
        for (int o = 0; o < 16; o++) {
            float acc = b_se[o];
            #pragma unroll
            for (int i = 0; i < SID; i++) acc += sfv[i] * W_se[i * 16 + o];
            seA[(wid * 32 + lane) * 16 + o] = fmaxf(acc, 0.f);
        }
    }
    __syncthreads();

    // h0 in C-frag state layout
    float h[16];
    #pragma unroll
    for (int mt = 0; mt < 2; mt++)
    #pragma unroll
    for (int e = 0; e < 8; e++) {
        int col = 2 * c + (e & 1) + ((e >> 2) & 1) * 8;
        int rl = wid * 32 + 16 * mt + g + ((e >> 1) & 1) * 8;
        float acc = b_i[col];
        #pragma unroll
        for (int i = 0; i < 16; i++) acc += seA[rl * 16 + i] * W_i[i * 16 + col];
        h[mt * 8 + e] = acc;
    }
    // cg (b1 + se@W1[16:32]) into C-frag-ordered smem
    const char* cgT = smem + SM_CG + wid * 8192 + lane * 16;
    for (int mt = 0; mt < 2; mt++)
    for (int nt = 0; nt < 8; nt++) {
        float v[4];
        #pragma unroll
        for (int q = 0; q < 4; q++) {
            int j = 8 * nt + 2 * c + (q & 1);
            int rl = wid * 32 + 16 * mt + g + (q >> 1) * 8;
            float acc = b1[j];
            #pragma unroll
            for (int i = 0; i < 16; i++) acc += seA[rl * 16 + i] * W1[(16 + i) * 64 + j];
            v[q] = acc;
        }
        *(float4*)(smem + SM_CG + (wid * 16 + mt * 8 + nt) * 512 + lane * 16)
            = make_float4(v[0], v[1], v[2], v[3]);
    }

    // register-resident B fragments
    u32 b1h[16], b1l[16];
    float w1dA[8], w1dB[8];
    #pragma unroll
    for (int nt = 0; nt < 8; nt++) {
        bf16split2(W1[(2 * c) * 64 + 8 * nt + g], W1[(2 * c + 1) * 64 + 8 * nt + g],
                   b1h[nt * 2], b1l[nt * 2]);
        bf16split2(W1[(2 * c + 8) * 64 + 8 * nt + g], W1[(2 * c + 9) * 64 + 8 * nt + g],
                   b1h[nt * 2 + 1], b1l[nt * 2 + 1]);
        w1dA[nt] = W1[32 * 64 + 8 * nt + 2 * c];
        w1dB[nt] = W1[32 * 64 + 8 * nt + 2 * c + 1];
    }
    u32 b2h[16], b2l[16];
    #pragma unroll
    for (int kt = 0; kt < 4; kt++)
    #pragma unroll
    for (int nt2 = 0; nt2 < 2; nt2++) {
        int o = 8 * nt2 + g;
        bf16split2(W2[(16 * kt + 2 * c) * 16 + o], W2[(16 * kt + 2 * c + 1) * 16 + o],
                   b2h[kt * 4 + nt2 * 2], b2l[kt * 4 + nt2 * 2]);
        bf16split2(W2[(16 * kt + 2 * c + 8) * 16 + o], W2[(16 * kt + 2 * c + 9) * 16 + o],
                   b2h[kt * 4 + nt2 * 2 + 1], b2l[kt * 4 + nt2 * 2 + 1]);
    }
    float b2q[4] = { b2[2 * c], b2[2 * c + 1], b2[2 * c + 8], b2[2 * c + 9] };
    float wrq[4] = { Wr[2 * c], Wr[2 * c + 1], Wr[2 * c + 8], Wr[2 * c + 9] };
    const float brv = br[0];

    float itm[N_INJ], idn[N_INJ];
    #pragma unroll
    for (int n = 0; n < N_INJ; n++) {
        itm[n] = it_g[ro * N_INJ + n];
        idn[n] = id_g[ro * N_INJ + n];
    }
    __syncthreads();

    if (!valid) return;   // masked warps (1024..1028) exit after last CTA sync

    writeout(h, wrq, brv, rbase, g, c, 0, out);

    const float A21 = 0.2f, A31 = 0.075f, A32 = 0.225f;
    const float A41 = (float)(44.0/45.0), A42 = (float)(-56.0/15.0), A43 = (float)(32.0/9.0);
    const float A51 = (float)(19372.0/6561.0), A52 = (float)(-25360.0/2187.0),
                A53 = (float)(64448.0/6561.0), A54 = (float)(-212.0/729.0);
    const float A61 = (float)(9017.0/3168.0), A62 = (float)(-355.0/33.0),
                A63 = (float)(46732.0/5247.0), A64 = (float)(49.0/176.0),
                A65 = (float)(-5103.0/18656.0);
    const float B1c = (float)(35.0/384.0), B3c = (float)(500.0/1113.0),
                B4c = (float)(125.0/192.0), B5c = (float)(-2187.0/6784.0),
                B6c = (float)(11.0/84.0);
    const float C2 = 0.2f, C3 = 0.3f, C4 = 0.8f, C5 = (float)(8.0/9.0);

    float k1[16], k2[16], k3[16], k4[16], k5[16], y[16];

    #pragma unroll 1
    for (int step = 0; step < T_STEPS - 1; ++step) {
        float t0 = smT[step], t1 = smT[step + 1];
        float dt = (t1 - t0) * 0.5f;
        #pragma unroll 1
        for (int sub = 0; sub < 2; ++sub) {
            float tv = t0 + sub * dt;
            feval(tv, h, k1, b1h, b1l, b2h, b2l, w1dA, w1dB, b2q, cgT, itm, idn, g);
            #pragma unroll
            for (int i = 0; i < 16; i++) y[i] = fmaf(dt * A21, k1[i], h[i]);
            feval(tv + C2 * dt, y, k2, b1h, b1l, b2h, b2l, w1dA, w1dB, b2q, cgT, itm, idn, g);
            #pragma unroll
            for (int i = 0; i < 16; i++)
                y[i] = fmaf(dt * A31, k1[i], fmaf(dt * A32, k2[i], h[i]));
            feval(tv + C3 * dt, y, k3, b1h, b1l, b2h, b2l, w1dA, w1dB, b2q, cgT, itm, idn, g);
            #pragma unroll
            for (int i = 0; i < 16; i++) {
                float a = fmaf(dt * A43, k3[i], h[i]);
                a = fmaf(dt * A42, k2[i], a);
                y[i] = fmaf(dt * A41, k1[i], a);
            }
            feval(tv + C4 * dt, y, k4, b1h, b1l, b2h, b2l, w1dA, w1dB, b2q, cgT, itm, idn, g);
            #pragma unroll
            for (int i = 0; i < 16; i++) {
                float a = fmaf(dt * A54, k4[i], h[i]);
                a = fmaf(dt * A53, k3[i], a);
                a = fmaf(dt * A52, k2[i], a);
                y[i] = fmaf(dt * A51, k1[i], a);
            }
            feval(tv + C5 * dt, y, k5, b1h, b1l, b2h, b2l, w1dA, w1dB, b2q, cgT, itm, idn, g);
            #pragma unroll
            for (int i = 0; i < 16; i++) {
                float a = fmaf(dt * A65, k5[i], h[i]);
                a = fmaf(dt * A64, k4[i], a);
                a = fmaf(dt * A63, k3[i], a);
                a = fmaf(dt * A62, k2[i], a);
                y[i] = fmaf(dt * A61, k1[i], a);
            }
            feval(tv + dt, y, k2, b1h, b1l, b2h, b2l, w1dA, w1dB, b2q, cgT, itm, idn, g);
            #pragma unroll
            for (int i = 0; i < 16; i++) {
                float a = fmaf(dt * B6c, k2[i], h[i]);
                a = fmaf(dt * B5c, k5[i], a);
                a = fmaf(dt * B4c, k4[i], a);
                a = fmaf(dt * B3c, k3[i], a);
                h[i] = fmaf(dt * B1c, k1[i], a);
            }
        }
        writeout(h, wrq, brv, rbase, g, c, step + 1, out);
    }
}

extern "C" void kernel_launch(void* const* d_in, const int* in_sizes, int n_in,
                              void* d_out, int out_size)
{
    (void)in_sizes; (void)n_in; (void)out_size;
    cudaFuncSetAttribute(neural_ode_66236985639756,
                         cudaFuncAttributeMaxDynamicSharedMemorySize, SM_TOTAL);
    neural_ode_66236985639756<<<GRID, BLOCK, SM_TOTAL>>>(
        (const float*)d_in[0],  (const float*)d_in[1],
        (const float*)d_in[2],  (const float*)d_in[3],
        (const float*)d_in[4],  (const float*)d_in[5],
        (const float*)d_in[6],  (const float*)d_in[7],
        (const float*)d_in[8],  (const float*)d_in[9],
        (const float*)d_in[10], (const float*)d_in[11],
        (const float*)d_in[12], (const float*)d_in[13],
        (float*)d_out);
}

// round 11
// speedup vs baseline: 1.3345x; 1.3345x over previous
#include <cuda_runtime.h>

#define T_STEPS 64
#define N_INJ 8
#define SID 7
#define BLOCK 256
#define GRID 128

#define SM_T    0
#define SM_W1D  256
#define SM_B2H  512
#define SM_B2L  2560
#define SM_SE   4608
#define SM_CG   20992
#define SM_TOTAL (SM_CG + 8*8192)   // 86528 B

typedef unsigned u32;

__device__ __forceinline__ void bf16split2(float x0, float x1, u32& h, u32& l) {
    asm("cvt.rn.bf16x2.f32 %0, %1, %2;" : "=r"(h) : "f"(x1), "f"(x0));
    float h0 = __uint_as_float(h << 16);
    float h1 = __uint_as_float(h & 0xffff0000u);
    asm("cvt.rn.bf16x2.f32 %0, %1, %2;" : "=r"(l) : "f"(x1 - h1), "f"(x0 - h0));
}
__device__ __forceinline__ float tanhap(float x) {
    float r; asm("tanh.approx.f32 %0,%1;" : "=f"(r) : "f"(x)); return r;
}
__device__ __forceinline__ void mma4(float& c0, float& c1, float& c2, float& c3,
                                     const u32* a, u32 b0, u32 b1) {
    asm volatile("mma.sync.aligned.m16n8k16.row.col.f32.bf16.bf16.f32 "
        "{%0,%1,%2,%3},{%4,%5,%6,%7},{%8,%9},{%0,%1,%2,%3};"
        : "+f"(c0), "+f"(c1), "+f"(c2), "+f"(c3)
        : "r"(a[0]), "r"(a[1]), "r"(a[2]), "r"(a[3]), "r"(b0), "r"(b1));
}

// one MLP eval: ys[16] (C-frag state) -> ko[16]
__device__ __forceinline__ void feval(
    float tv, const float* __restrict__ ys, float* __restrict__ ko,
    const u32* __restrict__ b1h, const u32* __restrict__ b1l,
    const float* __restrict__ b2q, const char* __restrict__ smem,
    const char* __restrict__ cgT,
    const float* __restrict__ itm, const float* __restrict__ idn,
    int g, int c, int lane)
{
    float dose = 0.f;
    #pragma unroll
    for (int n = 0; n < N_INJ; n++) {
        float d = tv - itm[n];
        dose += idn[n] * __expf(-0.5f * d * d);
    }
    dose = fminf(fmaxf(dose, 0.f), 100.f);

    #pragma unroll
    for (int mt = 0; mt < 2; mt++) {
        float d0 = __shfl_sync(0xffffffffu, dose, 16 * mt + g);
        float d1 = __shfl_sync(0xffffffffu, dose, 16 * mt + g + 8);
        const float* y = ys + mt * 8;
        u32 a1h[4], a1l[4];
        bf16split2(y[0], y[1], a1h[0], a1l[0]);
        bf16split2(y[2], y[3], a1h[1], a1l[1]);
        bf16split2(y[4], y[5], a1h[2], a1l[2]);
        bf16split2(y[6], y[7], a1h[3], a1l[3]);

        u32 a2h[16], a2l[16];
        #pragma unroll
        for (int nt = 0; nt < 8; nt++) {
            float4 cg = *(const float4*)(cgT + (mt * 8 + nt) * 512);
            float2 wd = *(const float2*)(smem + SM_W1D + nt * 32 + c * 8);
            float z0 = fmaf(d0, wd.x, cg.x);
            float z1 = fmaf(d0, wd.y, cg.y);
            float z2 = fmaf(d1, wd.x, cg.z);
            float z3 = fmaf(d1, wd.y, cg.w);
            mma4(z0, z1, z2, z3, a1h, b1h[nt * 2], b1h[nt * 2 + 1]);
            mma4(z0, z1, z2, z3, a1h, b1l[nt * 2], b1l[nt * 2 + 1]);
            mma4(z0, z1, z2, z3, a1l, b1h[nt * 2], b1h[nt * 2 + 1]);
            float t0 = tanhap(z0), t1 = tanhap(z1);
            float t2 = tanhap(z2), t3 = tanhap(z3);
            int base = (nt >> 1) * 4 + (nt & 1) * 2;
            bf16split2(t0, t1, a2h[base], a2l[base]);
            bf16split2(t2, t3, a2h[base + 1], a2l[base + 1]);
        }
        // layer 2: kt outer so each B-frag uint4 is loaded once
        float cA0 = b2q[0], cA1 = b2q[1], cA2 = cA0, cA3 = cA1;   // cols 0..7
        float cB0 = b2q[2], cB1 = b2q[3], cB2 = cB0, cB3 = cB1;   // cols 8..15
        #pragma unroll
        for (int kt = 0; kt < 4; kt++) {
            uint4 bh = *(const uint4*)(smem + SM_B2H + kt * 512 + lane * 16);
            uint4 bl = *(const uint4*)(smem + SM_B2L + kt * 512 + lane * 16);
            mma4(cA0, cA1, cA2, cA3, a2h + kt * 4, bh.x, bh.y);
            mma4(cA0, cA1, cA2, cA3, a2h + kt * 4, bl.x, bl.y);
            mma4(cA0, cA1, cA2, cA3, a2l + kt * 4, bh.x, bh.y);
            mma4(cB0, cB1, cB2, cB3, a2h + kt * 4, bh.z, bh.w);
            mma4(cB0, cB1, cB2, cB3, a2h + kt * 4, bl.z, bl.w);
            mma4(cB0, cB1, cB2, cB3, a2l + kt * 4, bh.z, bh.w);
        }
        ko[mt * 8 + 0] = cA0;  ko[mt * 8 + 1] = cA1;
        ko[mt * 8 + 2] = cA2;  ko[mt * 8 + 3] = cA3;
        ko[mt * 8 + 4] = cB0;  ko[mt * 8 + 5] = cB1;
        ko[mt * 8 + 6] = cB2;  ko[mt * 8 + 7] = cB3;
    }
}

__device__ __forceinline__ void writeout(
    const float* __restrict__ h, const float* __restrict__ wrq, float brv,
    int rbase, int g, int c, int step, float* __restrict__ out)
{
    #pragma unroll
    for (int mt = 0; mt < 2; mt++)
    #pragma unroll
    for (int rh = 0; rh < 2; rh++) {
        float p = h[mt * 8 + rh * 2 + 0] * wrq[0] + h[mt * 8 + rh * 2 + 1] * wrq[1]
                + h[mt * 8 + 4 + rh * 2 + 0] * wrq[2] + h[mt * 8 + 4 + rh * 2 + 1] * wrq[3];
        p += __shfl_xor_sync(0xffffffffu, p, 1);
        p += __shfl_xor_sync(0xffffffffu, p, 2);
        if (c == 0)
            out[(rbase + 16 * mt + g + 8 * rh) * T_STEPS + step] = fmaxf(brv + p, 0.f);
    }
}

extern "C" __global__ void __launch_bounds__(BLOCK, 1)
neural_ode_66236985639756(
    const float* __restrict__ t_g,  const float* __restrict__ sf_g,
    const float* __restrict__ it_g, const float* __restrict__ id_g,
    const float* __restrict__ W_se, const float* __restrict__ b_se,
    const float* __restrict__ W_i,  const float* __restrict__ b_i,
    const float* __restrict__ W1,   const float* __restrict__ b1,
    const float* __restrict__ W2,   const float* __restrict__ b2,
    const float* __restrict__ Wr,   const float* __restrict__ br,
    float* __restrict__ out)
{
    extern __shared__ __align__(16) char smem[];
    float* smT = (float*)(smem + SM_T);
    float* seA = (float*)(smem + SM_SE);
    const int tid = threadIdx.x;
    const int wid = tid >> 5;
    const int lane = tid & 31;
    const int g = lane >> 2;
    const int c = lane & 3;
    const int rbase = blockIdx.x * BLOCK + wid * 32;
    const int ro = rbase + lane;

    for (int i = tid; i < T_STEPS; i += BLOCK) smT[i] = t_g[i];

    // layer-2 weight fragments + dose weights -> smem (one copy per CTA)
    if (wid == 0) {
        #pragma unroll
        for (int kt = 0; kt < 4; kt++) {
            uint4 vh, vl;
            int o0 = g, o1 = 8 + g;
            bf16split2(W2[(16 * kt + 2 * c) * 16 + o0],
                       W2[(16 * kt + 2 * c + 1) * 16 + o0], vh.x, vl.x);
            bf16split2(W2[(16 * kt + 2 * c + 8) * 16 + o0],
                       W2[(16 * kt + 2 * c + 9) * 16 + o0], vh.y, vl.y);
            bf16split2(W2[(16 * kt + 2 * c) * 16 + o1],
                       W2[(16 * kt + 2 * c + 1) * 16 + o1], vh.z, vl.z);
            bf16split2(W2[(16 * kt + 2 * c + 8) * 16 + o1],
                       W2[(16 * kt + 2 * c + 9) * 16 + o1], vh.w, vl.w);
            *(uint4*)(smem + SM_B2H + kt * 512 + lane * 16) = vh;
            *(uint4*)(smem + SM_B2L + kt * 512 + lane * 16) = vl;
        }
    }
    if (tid < 4) {
        #pragma unroll
        for (int nt = 0; nt < 8; nt++)
            *(float2*)(smem + SM_W1D + nt * 32 + tid * 8) =
                make_float2(W1[32 * 64 + 8 * nt + 2 * tid],
                            W1[32 * 64 + 8 * nt + 2 * tid + 1]);
    }

    // own-row static embed -> smem
    {
        float sfv[SID];
        #pragma unroll
        for (int i = 0; i < SID; i++) sfv[i] = sf_g[ro * SID + i];
        #pragma unroll
        for (int o = 0; o < 16; o++) {
            float acc = b_se[o];
            #pragma unroll
            for (int i = 0; i < SID; i++) acc += sfv[i] * W_se[i * 16 + o];
            seA[(wid * 32 + lane) * 16 + o] = fmaxf(acc, 0.f);
        }
    }
    __syncthreads();

    // h0 in C-frag state layout
    float h[16];
    #pragma unroll
    for (int mt = 0; mt < 2; mt++)
    #pragma unroll
    for (int e = 0; e < 8; e++) {
        int col = 2 * c + (e & 1) + ((e >> 2) & 1) * 8;
        int rl = wid * 32 + 16 * mt + g + ((e >> 1) & 1) * 8;
        float acc = b_i[col];
        #pragma unroll
        for (int i = 0; i < 16; i++) acc += seA[rl * 16 + i] * W_i[i * 16 + col];
        h[mt * 8 + e] = acc;
    }
    // cg (b1 + se@W1[16:32]) into C-frag-ordered smem
    const char* cgT = smem + SM_CG + wid * 8192 + lane * 16;
    for (int mt = 0; mt < 2; mt++)
    for (int nt = 0; nt < 8; nt++) {
        float v[4];
        #pragma unroll
        for (int q = 0; q < 4; q++) {
            int j = 8 * nt + 2 * c + (q & 1);
            int rl = wid * 32 + 16 * mt + g + (q >> 1) * 8;
            float acc = b1[j];
            #pragma unroll
            for (int i = 0; i < 16; i++) acc += seA[rl * 16 + i] * W1[(16 + i) * 64 + j];
            v[q] = acc;
        }
        *(float4*)(smem + SM_CG + (wid * 16 + mt * 8 + nt) * 512 + lane * 16)
            = make_float4(v[0], v[1], v[2], v[3]);
    }

    // register-resident layer-1 B fragments
    u32 b1h[16], b1l[16];
    #pragma unroll
    for (int nt = 0; nt < 8; nt++) {
        bf16split2(W1[(2 * c) * 64 + 8 * nt + g], W1[(2 * c + 1) * 64 + 8 * nt + g],
                   b1h[nt * 2], b1l[nt * 2]);
        bf16split2(W1[(2 * c + 8) * 64 + 8 * nt + g], W1[(2 * c + 9) * 64 + 8 * nt + g],
                   b1h[nt * 2 + 1], b1l[nt * 2 + 1]);
    }
    float b2q[4] = { b2[2 * c], b2[2 * c + 1], b2[2 * c + 8], b2[2 * c + 9] };
    float wrq[4] = { Wr[2 * c], Wr[2 * c + 1], Wr[2 * c + 8], Wr[2 * c + 9] };
    const float brv = br[0];

    float itm[N_INJ], idn[N_INJ];
    #pragma unroll
    for (int n = 0; n < N_INJ; n++) {
        itm[n] = it_g[ro * N_INJ + n];
        idn[n] = id_g[ro * N_INJ + n];
    }
    __syncthreads();

    writeout(h, wrq, brv, rbase, g, c, 0, out);

    const float A21 = 0.2f, A31 = 0.075f, A32 = 0.225f;
    const float A41 = (float)(44.0/45.0), A42 = (float)(-56.0/15.0), A43 = (float)(32.0/9.0);
    const float A51 = (float)(19372.0/6561.0), A52 = (float)(-25360.0/2187.0),
                A53 = (float)(64448.0/6561.0), A54 = (float)(-212.0/729.0);
    const float A61 = (float)(9017.0/3168.0), A62 = (float)(-355.0/33.0),
                A63 = (float)(46732.0/5247.0), A64 = (float)(49.0/176.0),
                A65 = (float)(-5103.0/18656.0);
    const float B1c = (float)(35.0/384.0), B3c = (float)(500.0/1113.0),
                B4c = (float)(125.0/192.0), B5c = (float)(-2187.0/6784.0),
                B6c = (float)(11.0/84.0);
    const float C2 = 0.2f, C3 = 0.3f, C4 = 0.8f, C5 = (float)(8.0/9.0);

    float k1[16], k2[16], k3[16], k4[16], k5[16], y[16];

    #pragma unroll 1
    for (int step = 0; step < T_STEPS - 1; ++step) {
        float t0 = smT[step], t1 = smT[step + 1];
        float dt = (t1 - t0) * 0.5f;
        #pragma unroll 1
        for (int sub = 0; sub < 2; ++sub) {
            float tv = t0 + sub * dt;
            feval(tv, h, k1, b1h, b1l, b2q, smem, cgT, itm, idn, g, c, lane);
            #pragma unroll
            for (int i = 0; i < 16; i++) y[i] = fmaf(dt * A21, k1[i], h[i]);
            feval(tv + C2 * dt, y, k2, b1h, b1l, b2q, smem, cgT, itm, idn, g, c, lane);
            #pragma unroll
            for (int i = 0; i < 16; i++)
                y[i] = fmaf(dt * A31, k1[i], fmaf(dt * A32, k2[i], h[i]));
            feval(tv + C3 * dt, y, k3, b1h, b1l, b2q, smem, cgT, itm, idn, g, c, lane);
            #pragma unroll
            for (int i = 0; i < 16; i++) {
                float a = fmaf(dt * A43, k3[i], h[i]);
                a = fmaf(dt * A42, k2[i], a);
                y[i] = fmaf(dt * A41, k1[i], a);
            }
            feval(tv + C4 * dt, y, k4, b1h, b1l, b2q, smem, cgT, itm, idn, g, c, lane);
            #pragma unroll
            for (int i = 0; i < 16; i++) {
                float a = fmaf(dt * A54, k4[i], h[i]);
                a = fmaf(dt * A53, k3[i], a);
                a = fmaf(dt * A52, k2[i], a);
                y[i] = fmaf(dt * A51, k1[i], a);
            }
            feval(tv + C5 * dt, y, k5, b1h, b1l, b2q, smem, cgT, itm, idn, g, c, lane);
            #pragma unroll
            for (int i = 0; i < 16; i++) {
                float a = fmaf(dt * A65, k5[i], h[i]);
                a = fmaf(dt * A64, k4[i], a);
                a = fmaf(dt * A63, k3[i], a);
                a = fmaf(dt * A62, k2[i], a);
                y[i] = fmaf(dt * A61, k1[i], a);
            }
            feval(tv + dt, y, k2, b1h, b1l, b2q, smem, cgT, itm, idn, g, c, lane);
            #pragma unroll
            for (int i = 0; i < 16; i++) {
                float a = fmaf(dt * B6c, k2[i], h[i]);
                a = fmaf(dt * B5c, k5[i], a);
                a = fmaf(dt * B4c, k4[i], a);
                a = fmaf(dt * B3c, k3[i], a);
                h[i] = fmaf(dt * B1c, k1[i], a);
            }
        }
        writeout(h, wrq, brv, rbase, g, c, step + 1, out);
    }
}

extern "C" void kernel_launch(void* const* d_in, const int* in_sizes, int n_in,
                              void* d_out, int out_size)
{
    (void)in_sizes; (void)n_in; (void)out_size;
    cudaFuncSetAttribute(neural_ode_66236985639756,
                         cudaFuncAttributeMaxDynamicSharedMemorySize, SM_TOTAL);
    neural_ode_66236985639756<<<GRID, BLOCK, SM_TOTAL>>>(
        (const float*)d_in[0],  (const float*)d_in[1],
        (const float*)d_in[2],  (const float*)d_in[3],
        (const float*)d_in[4],  (const float*)d_in[5],
        (const float*)d_in[6],  (const float*)d_in[7],
        (const float*)d_in[8],  (const float*)d_in[9],
        (const float*)d_in[10], (const float*)d_in[11],
        (const float*)d_in[12], (const float*)d_in[13],
        (float*)d_out);
}